// round 2
// baseline (speedup 1.0000x reference)
#include <cuda_runtime.h>

// DentateGyrus granule-cell spike kernel.
//
// Reference algebra:
//   spike[i] = (v_new[i] >= 30) ? 1 : 0   with
//   v_new    = v + 0.5*(0.04 v^2 + 5 v + 140 - u + 10*(W@ec))
// The reference's top-K sparsification is an identity on a binary vector:
//   if >=K spikes  -> threshold == 1.0 -> (s>=1)*s == s
//   if  <K spikes  -> threshold == 0.0 -> (s>=0)*s == 1*s == s
// Inputs 4..7 (recovery tau, coupling, reset voltage, AHP jump) only touch
// state that is never returned. So this is a pure HBM-bound GEMV (1 GiB of W)
// plus a pointwise Izhikevich threshold.

constexpr int ENTRY   = 8192;          // ec dimension (fixed by problem)
constexpr int THREADS = 256;
constexpr int WARPS   = THREADS / 32;  // 8 rows per block

__global__ __launch_bounds__(THREADS, 4)
void dentate_gyrus_kernel(const float* __restrict__ ec,
                          const float* __restrict__ W,
                          const float* __restrict__ v_in,
                          const float* __restrict__ u_in,
                          float* __restrict__ out,
                          int n_rows)
{
    // Stage ec (32 KB) in shared memory once per block; the W stream then owns
    // the L1/L2 read path and s_ec reads are conflict-free broadcasts.
    __shared__ float4 s_ec[ENTRY / 4];
    const float4* ec4 = reinterpret_cast<const float4*>(ec);
    #pragma unroll
    for (int i = threadIdx.x; i < ENTRY / 4; i += THREADS) {
        s_ec[i] = ec4[i];
    }
    __syncthreads();

    const int warp = threadIdx.x >> 5;
    const int lane = threadIdx.x & 31;
    const int row  = blockIdx.x * WARPS + warp;
    if (row >= n_rows) return;

    const float4* w4 = reinterpret_cast<const float4*>(W + (size_t)row * ENTRY);

    // 2048 float4 per row; 64 iterations per lane at stride 32.
    // Unroll 16 -> 16 independent 16B loads in flight per lane before the
    // accumulator chain serializes anything; __ldg keeps the single-use W
    // stream on the read-only path.
    float acc = 0.0f;
    #pragma unroll 16
    for (int j = lane; j < ENTRY / 4; j += 32) {
        const float4 a = __ldg(&w4[j]);
        const float4 b = s_ec[j];
        acc = fmaf(a.x, b.x, acc);
        acc = fmaf(a.y, b.y, acc);
        acc = fmaf(a.z, b.z, acc);
        acc = fmaf(a.w, b.w, acc);
    }

    // Warp tree reduction.
    #pragma unroll
    for (int off = 16; off > 0; off >>= 1)
        acc += __shfl_xor_sync(0xFFFFFFFFu, acc, off);

    if (lane == 0) {
        const float I  = acc * 10.0f;
        const float v  = v_in[row];
        const float u  = u_in[row];
        const float dv = 0.04f * v * v + 5.0f * v + 140.0f - u + I;
        const float vn = fmaf(dv, 0.5f, v);          // DT = 0.5
        out[row] = (vn >= 30.0f) ? 1.0f : 0.0f;
    }
}

extern "C" void kernel_launch(void* const* d_in, const int* in_sizes, int n_in,
                              void* d_out, int out_size)
{
    // metadata order:
    // 0: ec_spike_vector (8192)
    // 1: W (32768*8192)
    // 2: membrane_potential (32768)
    // 3: recovery_variable (32768)
    // 4: recovery_time_constant       (dead for output)
    // 5: subthreshold_coupling        (dead)
    // 6: spike_reset_voltage          (dead)
    // 7: after_hyperpolarization_jump (dead)
    const float* ec = (const float*)d_in[0];
    const float* W  = (const float*)d_in[1];
    const float* v  = (const float*)d_in[2];
    const float* u  = (const float*)d_in[3];
    float* out      = (float*)d_out;

    const int n_rows = in_sizes[2];                 // 32768
    const int grid   = (n_rows + WARPS - 1) / WARPS; // 4096 blocks
    dentate_gyrus_kernel<<<grid, THREADS>>>(ec, W, v, u, out, n_rows);
}